// round 2
// baseline (speedup 1.0000x reference)
#include <cuda_runtime.h>
#include <cuda_bf16.h>
#include <math.h>

// Problem constants
#define B_  64
#define S_  2048
#define H_  512
#define M_  (B_ * S_)   // 131072 GEMM rows

// Scratch (device globals — no allocations allowed)
__device__ float g_comb[B_ * H_];   // dec_f + bh + bc + bs  per (b, n)
__device__ float g_e[B_ * S_];      // e_t logits

// ---------------------------------------------------------------------------
// Kernel 1: comb[b][n] = sum_h dec[b][h]*Ws[h][n] + bs[n] + bh[n] + bc[n]
// ---------------------------------------------------------------------------
__global__ void dec_comb_kernel(const float* __restrict__ dec,
                                const float* __restrict__ Ws,
                                const float* __restrict__ bs,
                                const float* __restrict__ bh,
                                const float* __restrict__ bc)
{
    int b = blockIdx.x;
    __shared__ float dh[H_];
    for (int i = threadIdx.x; i < H_; i += blockDim.x)
        dh[i] = dec[b * H_ + i];
    __syncthreads();

    for (int n = threadIdx.x; n < H_; n += blockDim.x) {
        float acc = 0.f;
        #pragma unroll 8
        for (int h = 0; h < H_; ++h)
            acc = fmaf(dh[h], Ws[h * H_ + n], acc);
        g_comb[b * H_ + n] = acc + bs[n] + bh[n] + bc[n];
    }
}

// ---------------------------------------------------------------------------
// Kernel 2: fused GEMM (enc @ Wh) -> tanh(+biases+cov*Wc) -> dot(v_w) -> e_t
// Tile: BM=128 rows, BN=128 cols (x4 chunks for N=512), BK=8, 256 threads, 8x8/thread
// ---------------------------------------------------------------------------
#define BM 128
#define BN 128
#define BK 8

__global__ __launch_bounds__(256, 2)
void attn_gemm_kernel(const float* __restrict__ A,    // [M_, H_] encoder_output
                      const float* __restrict__ Wh,   // [H_, H_]
                      const float* __restrict__ Wc,   // [H_]
                      const float* __restrict__ cov,  // [M_]
                      const float* __restrict__ v_w)  // [H_]
{
    __shared__ float As[BK][BM];
    __shared__ float Bs[BK][BN];
    __shared__ float ered[BM][17];   // padded reduction buffer

    const int tid   = threadIdx.x;
    const int tx    = tid & 15;      // 0..15  -> col group
    const int ty    = tid >> 4;      // 0..15  -> row group
    const int mBase = blockIdx.x * BM;
    const int b     = mBase >> 11;   // / 2048 (BM divides S)

    // A-tile load mapping: 128 rows x 8 cols = 256 float4
    const int arow  = tid >> 1;          // 0..127
    const int acol4 = (tid & 1) << 2;    // 0 or 4
    // B-tile load mapping: 8 rows x 128 cols = 256 float4
    const int brow  = tid >> 5;          // 0..7
    const int bcol4 = (tid & 31) << 2;   // 0..124

    // Per-thread row-local data
    float cov_row[8];
    #pragma unroll
    for (int i = 0; i < 8; ++i)
        cov_row[i] = cov[mBase + ty * 8 + i];

    float e_part[8];
    #pragma unroll
    for (int i = 0; i < 8; ++i) e_part[i] = 0.f;

    const float* combB = &g_comb[b * H_];

    for (int nc = 0; nc < H_ / BN; ++nc) {
        const int nBase = nc * BN;

        float acc[8][8];
        #pragma unroll
        for (int i = 0; i < 8; ++i)
            #pragma unroll
            for (int j = 0; j < 8; ++j) acc[i][j] = 0.f;

        for (int k0 = 0; k0 < H_; k0 += BK) {
            // load A tile (transposed into As[k][m])
            {
                const float4 va = *reinterpret_cast<const float4*>(
                    &A[(size_t)(mBase + arow) * H_ + k0 + acol4]);
                As[acol4 + 0][arow] = va.x;
                As[acol4 + 1][arow] = va.y;
                As[acol4 + 2][arow] = va.z;
                As[acol4 + 3][arow] = va.w;
            }
            // load B tile
            {
                const float4 vb = *reinterpret_cast<const float4*>(
                    &Wh[(size_t)(k0 + brow) * H_ + nBase + bcol4]);
                *reinterpret_cast<float4*>(&Bs[brow][bcol4]) = vb;
            }
            __syncthreads();

            #pragma unroll
            for (int kk = 0; kk < BK; ++kk) {
                float af[8], bf[8];
                #pragma unroll
                for (int i = 0; i < 8; ++i) af[i] = As[kk][ty * 8 + i];
                #pragma unroll
                for (int j = 0; j < 8; ++j) bf[j] = Bs[kk][tx * 8 + j];
                #pragma unroll
                for (int i = 0; i < 8; ++i)
                    #pragma unroll
                    for (int j = 0; j < 8; ++j)
                        acc[i][j] = fmaf(af[i], bf[j], acc[i][j]);
            }
            __syncthreads();
        }

        // Fused epilogue: tanh + v-dot partial accumulation
        #pragma unroll
        for (int j = 0; j < 8; ++j) {
            const int n  = nBase + tx * 8 + j;
            const float cb = combB[n];
            const float wc = Wc[n];
            const float vw = v_w[n];
            #pragma unroll
            for (int i = 0; i < 8; ++i) {
                float t = tanhf(acc[i][j] + cb + cov_row[i] * wc);
                e_part[i] = fmaf(vw, t, e_part[i]);
            }
        }
        __syncthreads();  // before tiles are reloaded next chunk
    }

    // Reduce e_part across the 16 tx-threads sharing each row
    #pragma unroll
    for (int i = 0; i < 8; ++i)
        ered[ty * 8 + i][tx] = e_part[i];
    __syncthreads();

    if (tid < BM) {
        float s = 0.f;
        #pragma unroll
        for (int t = 0; t < 16; ++t) s += ered[tid][t];
        g_e[mBase + tid] = s;
    }
}

// ---------------------------------------------------------------------------
// Kernel 3: per-batch softmax over S=2048 + coverage update.
// (v_b is a constant shift -> softmax-invariant -> dropped.)
// out[0 : B*S]      = a_t
// out[B*S : 2*B*S]  = coverage + a_t
// ---------------------------------------------------------------------------
__global__ __launch_bounds__(256)
void softmax_kernel(const float* __restrict__ cov, float* __restrict__ out)
{
    const int b   = blockIdx.x;
    const int tid = threadIdx.x;
    __shared__ float red[256];

    float local[8];
    float mx = -INFINITY;
    #pragma unroll
    for (int i = 0; i < 8; ++i) {
        local[i] = g_e[b * S_ + tid + i * 256];
        mx = fmaxf(mx, local[i]);
    }

    red[tid] = mx;
    __syncthreads();
    for (int s = 128; s > 0; s >>= 1) {
        if (tid < s) red[tid] = fmaxf(red[tid], red[tid + s]);
        __syncthreads();
    }
    const float m = red[0];
    __syncthreads();

    float sum = 0.f;
    #pragma unroll
    for (int i = 0; i < 8; ++i) {
        local[i] = expf(local[i] - m);
        sum += local[i];
    }
    red[tid] = sum;
    __syncthreads();
    for (int s = 128; s > 0; s >>= 1) {
        if (tid < s) red[tid] += red[tid + s];
        __syncthreads();
    }
    const float inv = 1.0f / red[0];

    #pragma unroll
    for (int i = 0; i < 8; ++i) {
        const int idx = b * S_ + tid + i * 256;
        const float a = local[i] * inv;
        out[idx]           = a;
        out[B_ * S_ + idx] = cov[idx] + a;
    }
}

// ---------------------------------------------------------------------------
// Launch
// ---------------------------------------------------------------------------
extern "C" void kernel_launch(void* const* d_in, const int* in_sizes, int n_in,
                              void* d_out, int out_size)
{
    const float* enc  = (const float*)d_in[0];   // [B,S,H]
    const float* dec  = (const float*)d_in[1];   // [B,H]
    const float* cov  = (const float*)d_in[2];   // [B,S]
    const float* Wh   = (const float*)d_in[3];   // [H,H]
    const float* bh   = (const float*)d_in[4];   // [H]
    const float* Ws   = (const float*)d_in[5];   // [H,H]
    const float* bs   = (const float*)d_in[6];   // [H]
    const float* Wc   = (const float*)d_in[7];   // [1,H] -> H floats
    const float* bc   = (const float*)d_in[8];   // [H]
    const float* v_w  = (const float*)d_in[9];   // [H]
    // d_in[10] = v_b : softmax-invariant, unused
    float* out = (float*)d_out;

    dec_comb_kernel<<<B_, 256>>>(dec, Ws, bs, bh, bc);
    attn_gemm_kernel<<<M_ / BM, 256>>>(enc, Wh, Wc, cov, v_w);
    softmax_kernel<<<B_, 256>>>(cov, out);
}

// round 6
// speedup vs baseline: 2.1966x; 2.1966x over previous
#include <cuda_runtime.h>
#include <cuda_bf16.h>
#include <math.h>
#include <stdint.h>

#define B_  64
#define S_  2048
#define H_  512
#define M_  (B_ * S_)

// ---------------- device scratch (no allocs allowed) ----------------
__device__ __nv_bfloat16 g_A0[(size_t)M_ * H_];   // 128 MB: enc hi (bf16)
__device__ __nv_bfloat16 g_A1[(size_t)M_ * H_];   // 128 MB: enc lo residual
__device__ __nv_bfloat16 g_B0[H_ * H_];           // Wh^T hi  [n][k]
__device__ __nv_bfloat16 g_B1[H_ * H_];           // Wh^T lo  [n][k]
__device__ float g_comb[B_ * H_];                 // dec@Ws + bs + bh + bc
__device__ float g_epart[4 * M_];                 // per-nc partial e sums

// ---------------- helpers ----------------
__device__ __forceinline__ uint32_t smem_u32(const void* p) {
    uint32_t a;
    asm("{ .reg .u64 t; cvta.to.shared.u64 t, %1; cvt.u32.u64 %0, t; }" : "=r"(a) : "l"(p));
    return a;
}
// pack two fp32 -> bf16x2 (e0 in low half / first element)
__device__ __forceinline__ uint32_t bf16x2_pack(float e0, float e1) {
    uint32_t r;
    asm("cvt.rn.bf16x2.f32 %0, %1, %2;" : "=r"(r) : "f"(e1), "f"(e0));
    return r;
}
// accurate tanh: 2 MUFU, rel err ~1e-7, saturates correctly
__device__ __forceinline__ float tanh_acc(float x) {
    float e = __expf(2.0f * x);
    return 1.0f - __fdividef(2.0f, e + 1.0f);
}
__device__ __forceinline__ void ldsm4(uint32_t* r, uint32_t addr) {
    asm volatile("ldmatrix.sync.aligned.m8n8.x4.shared.b16 {%0,%1,%2,%3}, [%4];"
                 : "=r"(r[0]), "=r"(r[1]), "=r"(r[2]), "=r"(r[3]) : "r"(addr));
}
__device__ __forceinline__ void mma_bf16(float* c, const uint32_t* a, uint32_t b0, uint32_t b1) {
    asm volatile(
        "mma.sync.aligned.m16n8k16.row.col.f32.bf16.bf16.f32 "
        "{%0,%1,%2,%3},{%4,%5,%6,%7},{%8,%9},{%0,%1,%2,%3};"
        : "+f"(c[0]), "+f"(c[1]), "+f"(c[2]), "+f"(c[3])
        : "r"(a[0]), "r"(a[1]), "r"(a[2]), "r"(a[3]), "r"(b0), "r"(b1));
}
__device__ __forceinline__ void cp16(uint32_t dst, const void* src) {
    asm volatile("cp.async.cg.shared.global [%0], [%1], 16;" :: "r"(dst), "l"(src));
}

// ---------------------------------------------------------------------------
// Pack A: enc fp32 -> g_A0 (bf16 hi), g_A1 (bf16 residual)
// ---------------------------------------------------------------------------
__global__ void apack_kernel(const float* __restrict__ A)
{
    const size_t i = (size_t)blockIdx.x * 256 + threadIdx.x;  // float4 index
    const float4 v = ((const float4*)A)[i];
    const float hx = __bfloat162float(__float2bfloat16_rn(v.x));
    const float hy = __bfloat162float(__float2bfloat16_rn(v.y));
    const float hz = __bfloat162float(__float2bfloat16_rn(v.z));
    const float hw = __bfloat162float(__float2bfloat16_rn(v.w));
    ((uint2*)g_A0)[i] = make_uint2(bf16x2_pack(hx, hy), bf16x2_pack(hz, hw));
    ((uint2*)g_A1)[i] = make_uint2(bf16x2_pack(v.x - hx, v.y - hy),
                                   bf16x2_pack(v.z - hz, v.w - hw));
}

// ---------------------------------------------------------------------------
// Pack B: Wh [k][n] fp32 -> g_B0/g_B1 [n][k] bf16 hi/lo (transpose)
// ---------------------------------------------------------------------------
__global__ void bpack_kernel(const float* __restrict__ Wh)
{
    const int n = blockIdx.x;               // 0..511
    for (int k = threadIdx.x; k < H_; k += 256) {
        const float v = Wh[(size_t)k * H_ + n];
        const float h = __bfloat162float(__float2bfloat16_rn(v));
        g_B0[n * H_ + k] = __float2bfloat16_rn(v);
        g_B1[n * H_ + k] = __float2bfloat16_rn(v - h);
    }
}

// ---------------------------------------------------------------------------
// comb[b][n] = dec[b] @ Ws[:,n] + bs + bh + bc
// ---------------------------------------------------------------------------
__global__ void dec_comb_kernel(const float* __restrict__ dec,
                                const float* __restrict__ Ws,
                                const float* __restrict__ bs,
                                const float* __restrict__ bh,
                                const float* __restrict__ bc)
{
    const int b  = blockIdx.x;
    const int nh = blockIdx.y;
    const int tid = threadIdx.x;
    __shared__ float dh[H_];
    __shared__ float red[4][64];

    dh[tid]       = dec[b * H_ + tid];
    dh[tid + 256] = dec[b * H_ + tid + 256];
    __syncthreads();

    const int nl = tid & 63;
    const int n  = nh * 64 + nl;
    const int ks = tid >> 6;
    float acc = 0.f;
    #pragma unroll 8
    for (int h = ks * 128; h < ks * 128 + 128; ++h)
        acc = fmaf(dh[h], Ws[(size_t)h * H_ + n], acc);
    red[ks][nl] = acc;
    __syncthreads();
    if (ks == 0) {
        float s = red[0][nl] + red[1][nl] + red[2][nl] + red[3][nl];
        g_comb[b * H_ + n] = s + bs[n] + bh[n] + bc[n];
    }
}

// ---------------------------------------------------------------------------
// Main: 128x128x512 HMMA GEMM (3-term bf16 split) + fused tanh/v-dot epilogue
// grid (4 nc, 1024 m-tiles), 256 threads = 8 warps (warpM 0..1 x warpN 0..3)
// ---------------------------------------------------------------------------
#define KC        32
#define PITCH     80                      // 64B data + 16B pad -> ldmatrix conflict-free
#define MAT_BYTES (128 * PITCH)           // 10240
#define STAGE_BYTES (4 * MAT_BYTES)       // 40960 (A0|A1|B0|B1)
#define OFF_COMB  (2 * STAGE_BYTES)       // 81920
#define OFF_WC    (OFF_COMB + 512)
#define OFF_VW    (OFF_WC + 512)
#define OFF_ERED  (OFF_VW + 512)          // 83456
#define SMEM_DYN  (OFF_ERED + 128 * 16 * 4)  // 91648

__global__ __launch_bounds__(256, 1)
void attn_hmma_kernel(const float* __restrict__ cov,
                      const float* __restrict__ Wc,
                      const float* __restrict__ v_w)
{
    extern __shared__ char sm[];
    const uint32_t sbase = smem_u32(sm);
    const int tid  = threadIdx.x;
    const int wid  = tid >> 5;
    const int lane = tid & 31;
    const int nc     = blockIdx.x;          // 0..3  (fast-varying: A-tile L2 reuse)
    const int mBase  = blockIdx.y * 128;
    const int ncBase = nc * 128;
    const int b      = mBase >> 11;

    // epilogue constants for this n-chunk
    if (tid < 128) {
        ((float*)(sm + OFF_COMB))[tid] = g_comb[b * H_ + ncBase + tid];
        ((float*)(sm + OFF_WC))[tid]   = Wc[ncBase + tid];
        ((float*)(sm + OFF_VW))[tid]   = v_w[ncBase + tid];
    }

    // per-thread cp.async mapping: 2048 16B transfers/chunk, 8 per thread
    const char* srcs[8];
    uint32_t dsts[8];
    #pragma unroll
    for (int p = 0; p < 8; ++p) {
        const int idx = p * 256 + tid;
        const int mat = idx >> 9;          // 0:A0 1:A1 2:B0 3:B1
        const int r   = (idx >> 2) & 127;
        const int c   = idx & 3;
        const __nv_bfloat16* g;
        if      (mat == 0) g = g_A0 + (size_t)(mBase + r) * H_;
        else if (mat == 1) g = g_A1 + (size_t)(mBase + r) * H_;
        else if (mat == 2) g = g_B0 + (size_t)(ncBase + r) * H_;
        else               g = g_B1 + (size_t)(ncBase + r) * H_;
        srcs[p] = (const char*)(g + c * 8);
        dsts[p] = sbase + mat * MAT_BYTES + r * PITCH + c * 16;
    }

    const int warpM = wid >> 2;            // 0..1 -> 64 rows
    const int warpN = wid & 3;             // 0..3 -> 32 cols

    // ldmatrix offsets (relative to each matrix base, per stage add later)
    uint32_t offA[4][2], offB[2][2];
    {
        const int rowA = warpM * 64 + (lane & 7) + ((lane >> 3) & 1) * 8;
        const int cA   = (lane >> 4);                   // 0..1
        #pragma unroll
        for (int mI = 0; mI < 4; ++mI)
            #pragma unroll
            for (int s = 0; s < 2; ++s)
                offA[mI][s] = (uint32_t)((rowA + mI * 16) * PITCH + (s * 2 + cA) * 16);
        const int rowB = warpN * 32 + (lane & 7) + ((lane & 16) ? 8 : 0);
        const int cB   = (lane >> 3) & 1;
        #pragma unroll
        for (int p = 0; p < 2; ++p)
            #pragma unroll
            for (int s = 0; s < 2; ++s)
                offB[p][s] = (uint32_t)((rowB + p * 16) * PITCH + (s * 2 + cB) * 16);
    }

    float acc[4][4][4];
    #pragma unroll
    for (int i = 0; i < 4; ++i)
        #pragma unroll
        for (int j = 0; j < 4; ++j)
            #pragma unroll
            for (int q = 0; q < 4; ++q) acc[i][j][q] = 0.f;

    // prefetch chunk 0
    #pragma unroll
    for (int p = 0; p < 8; ++p) cp16(dsts[p], srcs[p]);
    asm volatile("cp.async.commit_group;" ::: "memory");

    #pragma unroll 1
    for (int c = 0; c < 16; ++c) {
        if (c < 15) {
            const uint32_t soff = ((c + 1) & 1) * STAGE_BYTES;
            #pragma unroll
            for (int p = 0; p < 8; ++p)
                cp16(dsts[p] + soff, srcs[p] + (c + 1) * 64);
            asm volatile("cp.async.commit_group;" ::: "memory");
            asm volatile("cp.async.wait_group 1;" ::: "memory");
        } else {
            asm volatile("cp.async.wait_group 0;" ::: "memory");
        }
        __syncthreads();

        const uint32_t st  = (c & 1) * STAGE_BYTES;
        const uint32_t a0b = sbase + st;
        const uint32_t a1b = a0b + MAT_BYTES;
        const uint32_t b0b = a0b + 2 * MAT_BYTES;
        const uint32_t b1b = a0b + 3 * MAT_BYTES;

        #pragma unroll
        for (int s = 0; s < 2; ++s) {
            uint32_t A0f[4][4], A1f[4][4], B0f[2][4], B1f[2][4];
            #pragma unroll
            for (int mI = 0; mI < 4; ++mI) ldsm4(A0f[mI], a0b + offA[mI][s]);
            #pragma unroll
            for (int p = 0; p < 2; ++p)    ldsm4(B0f[p], b0b + offB[p][s]);
            #pragma unroll
            for (int mI = 0; mI < 4; ++mI)
                #pragma unroll
                for (int nI = 0; nI < 4; ++nI)
                    mma_bf16(acc[mI][nI], A0f[mI], B0f[nI >> 1][(nI & 1) * 2], B0f[nI >> 1][(nI & 1) * 2 + 1]);
            #pragma unroll
            for (int mI = 0; mI < 4; ++mI) ldsm4(A1f[mI], a1b + offA[mI][s]);
            #pragma unroll
            for (int mI = 0; mI < 4; ++mI)
                #pragma unroll
                for (int nI = 0; nI < 4; ++nI)
                    mma_bf16(acc[mI][nI], A1f[mI], B0f[nI >> 1][(nI & 1) * 2], B0f[nI >> 1][(nI & 1) * 2 + 1]);
            #pragma unroll
            for (int p = 0; p < 2; ++p)    ldsm4(B1f[p], b1b + offB[p][s]);
            #pragma unroll
            for (int mI = 0; mI < 4; ++mI)
                #pragma unroll
                for (int nI = 0; nI < 4; ++nI)
                    mma_bf16(acc[mI][nI], A0f[mI], B1f[nI >> 1][(nI & 1) * 2], B1f[nI >> 1][(nI & 1) * 2 + 1]);
        }
        __syncthreads();
    }

    // ---- fused epilogue: tanh + v-dot, reduce across 16 column-threads ----
    const float* sComb = (const float*)(sm + OFF_COMB);
    const float* sWc   = (const float*)(sm + OFF_WC);
    const float* sVw   = (const float*)(sm + OFF_VW);
    float* ered = (float*)(sm + OFF_ERED);
    const int col = warpN * 4 + (lane & 3);

    #pragma unroll
    for (int mI = 0; mI < 4; ++mI) {
        const int mlo = warpM * 64 + mI * 16 + (lane >> 2);
        const float covlo = cov[mBase + mlo];
        const float covhi = cov[mBase + mlo + 8];
        float elo = 0.f, ehi = 0.f;
        #pragma unroll
        for (int nI = 0; nI < 4; ++nI) {
            #pragma unroll
            for (int t = 0; t < 2; ++t) {
                const int n = warpN * 32 + nI * 8 + (lane & 3) * 2 + t;   // FIXED: + warpN*32
                const float cb = sComb[n], wc = sWc[n], vw = sVw[n];
                elo = fmaf(vw, tanh_acc(acc[mI][nI][t]     + cb + covlo * wc), elo);
                ehi = fmaf(vw, tanh_acc(acc[mI][nI][t + 2] + cb + covhi * wc), ehi);
            }
        }
        ered[mlo * 16 + col]       = elo;
        ered[(mlo + 8) * 16 + col] = ehi;
    }
    __syncthreads();
    if (tid < 128) {
        float s = 0.f;
        #pragma unroll
        for (int t = 0; t < 16; ++t) s += ered[tid * 16 + t];
        g_epart[nc * M_ + mBase + tid] = s;
    }
}

// ---------------------------------------------------------------------------
// Softmax over S=2048 per batch + coverage update (v_b shift-invariant)
// ---------------------------------------------------------------------------
__global__ __launch_bounds__(256)
void softmax_kernel(const float* __restrict__ cov, float* __restrict__ out)
{
    const int b   = blockIdx.x;
    const int tid = threadIdx.x;
    __shared__ float red[256];

    float local[8];
    float mx = -INFINITY;
    #pragma unroll
    for (int i = 0; i < 8; ++i) {
        const int idx = b * S_ + tid + i * 256;
        local[i] = g_epart[idx] + g_epart[M_ + idx] + g_epart[2 * M_ + idx] + g_epart[3 * M_ + idx];
        mx = fmaxf(mx, local[i]);
    }
    red[tid] = mx;
    __syncthreads();
    for (int s = 128; s > 0; s >>= 1) {
        if (tid < s) red[tid] = fmaxf(red[tid], red[tid + s]);
        __syncthreads();
    }
    const float m = red[0];
    __syncthreads();

    float sum = 0.f;
    #pragma unroll
    for (int i = 0; i < 8; ++i) {
        local[i] = __expf(local[i] - m);
        sum += local[i];
    }
    red[tid] = sum;
    __syncthreads();
    for (int s = 128; s > 0; s >>= 1) {
        if (tid < s) red[tid] += red[tid + s];
        __syncthreads();
    }
    const float inv = 1.0f / red[0];

    #pragma unroll
    for (int i = 0; i < 8; ++i) {
        const int idx = b * S_ + tid + i * 256;
        const float a = local[i] * inv;
        out[idx]      = a;
        out[M_ + idx] = cov[idx] + a;
    }
}

// ---------------------------------------------------------------------------
extern "C" void kernel_launch(void* const* d_in, const int* in_sizes, int n_in,
                              void* d_out, int out_size)
{
    const float* enc = (const float*)d_in[0];
    const float* dec = (const float*)d_in[1];
    const float* cov = (const float*)d_in[2];
    const float* Wh  = (const float*)d_in[3];
    const float* bh  = (const float*)d_in[4];
    const float* Ws  = (const float*)d_in[5];
    const float* bs  = (const float*)d_in[6];
    const float* Wc  = (const float*)d_in[7];
    const float* bc  = (const float*)d_in[8];
    const float* v_w = (const float*)d_in[9];
    float* out = (float*)d_out;

    cudaFuncSetAttribute(attn_hmma_kernel,
                         cudaFuncAttributeMaxDynamicSharedMemorySize, SMEM_DYN);

    apack_kernel<<<M_ * H_ / 4 / 256, 256>>>(enc);
    bpack_kernel<<<H_, 256>>>(Wh);
    dec_comb_kernel<<<dim3(B_, 8), 256>>>(dec, Ws, bs, bh, bc);
    attn_hmma_kernel<<<dim3(4, M_ / 128), 256, SMEM_DYN>>>(cov, Wc, v_w);
    softmax_kernel<<<B_, 256>>>(cov, out);
}

// round 7
// speedup vs baseline: 2.2029x; 1.0028x over previous
#include <cuda_runtime.h>
#include <cuda_bf16.h>
#include <math.h>
#include <stdint.h>

#define B_  64
#define S_  2048
#define H_  512
#define M_  (B_ * S_)

// ---------------- device scratch (no allocs allowed) ----------------
__device__ __nv_bfloat16 g_A0[(size_t)M_ * H_];   // 128 MB: enc hi (bf16)
__device__ __nv_bfloat16 g_A1[(size_t)M_ * H_];   // 128 MB: enc lo residual
__device__ __nv_bfloat16 g_B0[H_ * H_];           // Wh^T hi  [n][k]
__device__ __nv_bfloat16 g_B1[H_ * H_];           // Wh^T lo  [n][k]
__device__ float g_comb[B_ * H_];                 // dec@Ws + bs + bh + bc
__device__ float g_epart[4 * M_];                 // per-nc partial e sums

// ---------------- helpers ----------------
__device__ __forceinline__ uint32_t smem_u32(const void* p) {
    uint32_t a;
    asm("{ .reg .u64 t; cvta.to.shared.u64 t, %1; cvt.u32.u64 %0, t; }" : "=r"(a) : "l"(p));
    return a;
}
__device__ __forceinline__ uint32_t bf16x2_pack(float e0, float e1) {
    uint32_t r;
    asm("cvt.rn.bf16x2.f32 %0, %1, %2;" : "=r"(r) : "f"(e1), "f"(e0));
    return r;
}
// accurate tanh: 2 MUFU, rel err ~1e-7, saturates correctly
__device__ __forceinline__ float tanh_acc(float x) {
    float e = __expf(2.0f * x);
    return 1.0f - __fdividef(2.0f, e + 1.0f);
}
__device__ __forceinline__ void ldsm4(uint32_t* r, uint32_t addr) {
    asm volatile("ldmatrix.sync.aligned.m8n8.x4.shared.b16 {%0,%1,%2,%3}, [%4];"
                 : "=r"(r[0]), "=r"(r[1]), "=r"(r[2]), "=r"(r[3]) : "r"(addr));
}
__device__ __forceinline__ void mma_bf16(float* c, const uint32_t* a, uint32_t b0, uint32_t b1) {
    asm volatile(
        "mma.sync.aligned.m16n8k16.row.col.f32.bf16.bf16.f32 "
        "{%0,%1,%2,%3},{%4,%5,%6,%7},{%8,%9},{%0,%1,%2,%3};"
        : "+f"(c[0]), "+f"(c[1]), "+f"(c[2]), "+f"(c[3])
        : "r"(a[0]), "r"(a[1]), "r"(a[2]), "r"(a[3]), "r"(b0), "r"(b1));
}
__device__ __forceinline__ void cp16(uint32_t dst, const void* src) {
    asm volatile("cp.async.cg.shared.global [%0], [%1], 16;" :: "r"(dst), "l"(src));
}

// ---------------------------------------------------------------------------
// Pack A: enc fp32 -> g_A0 (bf16 hi), g_A1 (bf16 residual)
// ---------------------------------------------------------------------------
__global__ void apack_kernel(const float* __restrict__ A)
{
    const size_t i = (size_t)blockIdx.x * 256 + threadIdx.x;  // float4 index
    const float4 v = ((const float4*)A)[i];
    const float hx = __bfloat162float(__float2bfloat16_rn(v.x));
    const float hy = __bfloat162float(__float2bfloat16_rn(v.y));
    const float hz = __bfloat162float(__float2bfloat16_rn(v.z));
    const float hw = __bfloat162float(__float2bfloat16_rn(v.w));
    ((uint2*)g_A0)[i] = make_uint2(bf16x2_pack(hx, hy), bf16x2_pack(hz, hw));
    ((uint2*)g_A1)[i] = make_uint2(bf16x2_pack(v.x - hx, v.y - hy),
                                   bf16x2_pack(v.z - hz, v.w - hw));
}

// ---------------------------------------------------------------------------
// Pack B: Wh [k][n] fp32 -> g_B0/g_B1 [n][k] bf16 hi/lo (transpose)
// ---------------------------------------------------------------------------
__global__ void bpack_kernel(const float* __restrict__ Wh)
{
    const int n = blockIdx.x;               // 0..511
    for (int k = threadIdx.x; k < H_; k += 256) {
        const float v = Wh[(size_t)k * H_ + n];
        const float h = __bfloat162float(__float2bfloat16_rn(v));
        g_B0[n * H_ + k] = __float2bfloat16_rn(v);
        g_B1[n * H_ + k] = __float2bfloat16_rn(v - h);
    }
}

// ---------------------------------------------------------------------------
// comb[b][n] = dec[b] @ Ws[:,n] + bs + bh + bc
// ---------------------------------------------------------------------------
__global__ void dec_comb_kernel(const float* __restrict__ dec,
                                const float* __restrict__ Ws,
                                const float* __restrict__ bs,
                                const float* __restrict__ bh,
                                const float* __restrict__ bc)
{
    const int b  = blockIdx.x;
    const int nh = blockIdx.y;
    const int tid = threadIdx.x;
    __shared__ float dh[H_];
    __shared__ float red[4][64];

    dh[tid]       = dec[b * H_ + tid];
    dh[tid + 256] = dec[b * H_ + tid + 256];
    __syncthreads();

    const int nl = tid & 63;
    const int n  = nh * 64 + nl;
    const int ks = tid >> 6;
    float acc = 0.f;
    #pragma unroll 8
    for (int h = ks * 128; h < ks * 128 + 128; ++h)
        acc = fmaf(dh[h], Ws[(size_t)h * H_ + n], acc);
    red[ks][nl] = acc;
    __syncthreads();
    if (ks == 0) {
        float s = red[0][nl] + red[1][nl] + red[2][nl] + red[3][nl];
        g_comb[b * H_ + n] = s + bs[n] + bh[n] + bc[n];
    }
}

// ---------------------------------------------------------------------------
// Main: 128x128x512 HMMA GEMM (3-term bf16 split) + fused tanh/v-dot epilogue
// grid (4 nc, 1024 m-tiles), 512 threads = 16 warps (warpM 0..3 x warpN 0..3)
// warp tile 32x32 -> more warps/SMSP to keep the tensor pipe fed.
// ---------------------------------------------------------------------------
#define PITCH     80                      // 64B data + 16B pad -> ldmatrix conflict-free
#define MAT_BYTES (128 * PITCH)           // 10240
#define STAGE_BYTES (4 * MAT_BYTES)       // 40960 (A0|A1|B0|B1)
#define OFF_COMB  (2 * STAGE_BYTES)       // 81920
#define OFF_WC    (OFF_COMB + 512)
#define OFF_VW    (OFF_WC + 512)
#define OFF_ERED  (OFF_VW + 512)          // 83456
#define SMEM_DYN  (OFF_ERED + 128 * 16 * 4)  // 91648

__global__ __launch_bounds__(512, 1)
void attn_hmma_kernel(const float* __restrict__ cov,
                      const float* __restrict__ Wc,
                      const float* __restrict__ v_w)
{
    extern __shared__ char sm[];
    const uint32_t sbase = smem_u32(sm);
    const int tid  = threadIdx.x;
    const int wid  = tid >> 5;
    const int lane = tid & 31;
    const int nc     = blockIdx.x;          // 0..3  (fast-varying: A-tile L2 reuse)
    const int mBase  = blockIdx.y * 128;
    const int ncBase = nc * 128;
    const int b      = mBase >> 11;

    // epilogue constants for this n-chunk
    if (tid < 128) {
        ((float*)(sm + OFF_COMB))[tid] = g_comb[b * H_ + ncBase + tid];
        ((float*)(sm + OFF_WC))[tid]   = Wc[ncBase + tid];
        ((float*)(sm + OFF_VW))[tid]   = v_w[ncBase + tid];
    }

    // per-thread cp.async mapping: 2048 16B transfers/chunk, 4 per thread
    const char* srcs[4];
    uint32_t dsts[4];
    #pragma unroll
    for (int p = 0; p < 4; ++p) {
        const int idx = p * 512 + tid;
        const int mat = idx >> 9;          // 0:A0 1:A1 2:B0 3:B1
        const int r   = (idx >> 2) & 127;
        const int c   = idx & 3;
        const __nv_bfloat16* g;
        if      (mat == 0) g = g_A0 + (size_t)(mBase + r) * H_;
        else if (mat == 1) g = g_A1 + (size_t)(mBase + r) * H_;
        else if (mat == 2) g = g_B0 + (size_t)(ncBase + r) * H_;
        else               g = g_B1 + (size_t)(ncBase + r) * H_;
        srcs[p] = (const char*)(g + c * 8);
        dsts[p] = sbase + mat * MAT_BYTES + r * PITCH + c * 16;
    }

    const int warpM = wid >> 2;            // 0..3 -> 32 rows
    const int warpN = wid & 3;             // 0..3 -> 32 cols

    // ldmatrix offsets (relative to each matrix base; add stage offset later)
    uint32_t offA[2][2], offB[2][2];
    {
        const int rowA = warpM * 32 + (lane & 7) + ((lane >> 3) & 1) * 8;
        const int cA   = (lane >> 4);                   // 0..1
        #pragma unroll
        for (int mI = 0; mI < 2; ++mI)
            #pragma unroll
            for (int s = 0; s < 2; ++s)
                offA[mI][s] = (uint32_t)((rowA + mI * 16) * PITCH + (s * 2 + cA) * 16);
        const int rowB = warpN * 32 + (lane & 7) + ((lane & 16) ? 8 : 0);
        const int cB   = (lane >> 3) & 1;
        #pragma unroll
        for (int p = 0; p < 2; ++p)
            #pragma unroll
            for (int s = 0; s < 2; ++s)
                offB[p][s] = (uint32_t)((rowB + p * 16) * PITCH + (s * 2 + cB) * 16);
    }

    float acc[2][4][4];
    #pragma unroll
    for (int i = 0; i < 2; ++i)
        #pragma unroll
        for (int j = 0; j < 4; ++j)
            #pragma unroll
            for (int q = 0; q < 4; ++q) acc[i][j][q] = 0.f;

    // prefetch chunk 0
    #pragma unroll
    for (int p = 0; p < 4; ++p) cp16(dsts[p], srcs[p]);
    asm volatile("cp.async.commit_group;" ::: "memory");

    #pragma unroll 1
    for (int c = 0; c < 16; ++c) {
        if (c < 15) {
            const uint32_t soff = ((c + 1) & 1) * STAGE_BYTES;
            #pragma unroll
            for (int p = 0; p < 4; ++p)
                cp16(dsts[p] + soff, srcs[p] + (c + 1) * 64);
            asm volatile("cp.async.commit_group;" ::: "memory");
            asm volatile("cp.async.wait_group 1;" ::: "memory");
        } else {
            asm volatile("cp.async.wait_group 0;" ::: "memory");
        }
        __syncthreads();

        const uint32_t st  = (c & 1) * STAGE_BYTES;
        const uint32_t a0b = sbase + st;
        const uint32_t a1b = a0b + MAT_BYTES;
        const uint32_t b0b = a0b + 2 * MAT_BYTES;
        const uint32_t b1b = a0b + 3 * MAT_BYTES;

        #pragma unroll
        for (int s = 0; s < 2; ++s) {
            uint32_t A0f[2][4], A1f[2][4], B0f[2][4], B1f[2][4];
            #pragma unroll
            for (int mI = 0; mI < 2; ++mI) ldsm4(A0f[mI], a0b + offA[mI][s]);
            #pragma unroll
            for (int p = 0; p < 2; ++p)    ldsm4(B0f[p], b0b + offB[p][s]);
            #pragma unroll
            for (int mI = 0; mI < 2; ++mI)
                #pragma unroll
                for (int nI = 0; nI < 4; ++nI)
                    mma_bf16(acc[mI][nI], A0f[mI], B0f[nI >> 1][(nI & 1) * 2], B0f[nI >> 1][(nI & 1) * 2 + 1]);
            #pragma unroll
            for (int mI = 0; mI < 2; ++mI) ldsm4(A1f[mI], a1b + offA[mI][s]);
            #pragma unroll
            for (int mI = 0; mI < 2; ++mI)
                #pragma unroll
                for (int nI = 0; nI < 4; ++nI)
                    mma_bf16(acc[mI][nI], A1f[mI], B0f[nI >> 1][(nI & 1) * 2], B0f[nI >> 1][(nI & 1) * 2 + 1]);
            #pragma unroll
            for (int p = 0; p < 2; ++p)    ldsm4(B1f[p], b1b + offB[p][s]);
            #pragma unroll
            for (int mI = 0; mI < 2; ++mI)
                #pragma unroll
                for (int nI = 0; nI < 4; ++nI)
                    mma_bf16(acc[mI][nI], A0f[mI], B1f[nI >> 1][(nI & 1) * 2], B1f[nI >> 1][(nI & 1) * 2 + 1]);
        }
        __syncthreads();
    }

    // ---- fused epilogue: tanh + v-dot, reduce across 16 column-threads ----
    const float* sComb = (const float*)(sm + OFF_COMB);
    const float* sWc   = (const float*)(sm + OFF_WC);
    const float* sVw   = (const float*)(sm + OFF_VW);
    float* ered = (float*)(sm + OFF_ERED);
    const int col = warpN * 4 + (lane & 3);

    #pragma unroll
    for (int mI = 0; mI < 2; ++mI) {
        const int mlo = warpM * 32 + mI * 16 + (lane >> 2);
        const float covlo = cov[mBase + mlo];
        const float covhi = cov[mBase + mlo + 8];
        float elo = 0.f, ehi = 0.f;
        #pragma unroll
        for (int nI = 0; nI < 4; ++nI) {
            #pragma unroll
            for (int t = 0; t < 2; ++t) {
                const int n = warpN * 32 + nI * 8 + (lane & 3) * 2 + t;
                const float cb = sComb[n], wc = sWc[n], vw = sVw[n];
                elo = fmaf(vw, tanh_acc(acc[mI][nI][t]     + cb + covlo * wc), elo);
                ehi = fmaf(vw, tanh_acc(acc[mI][nI][t + 2] + cb + covhi * wc), ehi);
            }
        }
        ered[mlo * 16 + col]       = elo;
        ered[(mlo + 8) * 16 + col] = ehi;
    }
    __syncthreads();
    if (tid < 128) {
        float s = 0.f;
        #pragma unroll
        for (int t = 0; t < 16; ++t) s += ered[tid * 16 + t];
        g_epart[nc * M_ + mBase + tid] = s;
    }
}

// ---------------------------------------------------------------------------
// Softmax over S=2048 per batch + coverage update (v_b shift-invariant)
// ---------------------------------------------------------------------------
__global__ __launch_bounds__(256)
void softmax_kernel(const float* __restrict__ cov, float* __restrict__ out)
{
    const int b   = blockIdx.x;
    const int tid = threadIdx.x;
    __shared__ float red[256];

    float local[8];
    float mx = -INFINITY;
    #pragma unroll
    for (int i = 0; i < 8; ++i) {
        const int idx = b * S_ + tid + i * 256;
        local[i] = g_epart[idx] + g_epart[M_ + idx] + g_epart[2 * M_ + idx] + g_epart[3 * M_ + idx];
        mx = fmaxf(mx, local[i]);
    }
    red[tid] = mx;
    __syncthreads();
    for (int s = 128; s > 0; s >>= 1) {
        if (tid < s) red[tid] = fmaxf(red[tid], red[tid + s]);
        __syncthreads();
    }
    const float m = red[0];
    __syncthreads();

    float sum = 0.f;
    #pragma unroll
    for (int i = 0; i < 8; ++i) {
        local[i] = __expf(local[i] - m);
        sum += local[i];
    }
    red[tid] = sum;
    __syncthreads();
    for (int s = 128; s > 0; s >>= 1) {
        if (tid < s) red[tid] += red[tid + s];
        __syncthreads();
    }
    const float inv = 1.0f / red[0];

    #pragma unroll
    for (int i = 0; i < 8; ++i) {
        const int idx = b * S_ + tid + i * 256;
        const float a = local[i] * inv;
        out[idx]      = a;
        out[M_ + idx] = cov[idx] + a;
    }
}

// ---------------------------------------------------------------------------
extern "C" void kernel_launch(void* const* d_in, const int* in_sizes, int n_in,
                              void* d_out, int out_size)
{
    const float* enc = (const float*)d_in[0];
    const float* dec = (const float*)d_in[1];
    const float* cov = (const float*)d_in[2];
    const float* Wh  = (const float*)d_in[3];
    const float* bh  = (const float*)d_in[4];
    const float* Ws  = (const float*)d_in[5];
    const float* bs  = (const float*)d_in[6];
    const float* Wc  = (const float*)d_in[7];
    const float* bc  = (const float*)d_in[8];
    const float* v_w = (const float*)d_in[9];
    float* out = (float*)d_out;

    cudaFuncSetAttribute(attn_hmma_kernel,
                         cudaFuncAttributeMaxDynamicSharedMemorySize, SMEM_DYN);

    apack_kernel<<<M_ * H_ / 4 / 256, 256>>>(enc);
    bpack_kernel<<<H_, 256>>>(Wh);
    dec_comb_kernel<<<dim3(B_, 8), 256>>>(dec, Ws, bs, bh, bc);
    attn_hmma_kernel<<<dim3(4, M_ / 128), 512, SMEM_DYN>>>(cov, Wc, v_w);
    softmax_kernel<<<B_, 256>>>(cov, out);
}